// round 2
// baseline (speedup 1.0000x reference)
#include <cuda_runtime.h>

#define OMEGA0 30.0f
#define BLK 256
#define IT 4

// ---------- packed f32x2 FMA (sm_103a FFMA2, only reachable via PTX) ----------
union F2u { float2 f; unsigned long long u; };

__device__ __forceinline__ float2 ffma2(float2 a, float2 b, float2 c) {
    F2u A, B, C, D;
    A.f = a; B.f = b; C.f = c;
    asm("fma.rn.f32x2 %0, %1, %2, %3;" : "=l"(D.u) : "l"(A.u), "l"(B.u), "l"(C.u));
    return D.f;
}

// ---------- sine: single-term range reduction (|k|<=3 -> abs err ~5e-7) ----------
__device__ __forceinline__ float fast_sin(float t) {
    float k = rintf(t * 0.15915494309189535f);      // t / (2*pi)
    t = fmaf(k, -6.2831855f, t);
    return __sinf(t);
}

__device__ __forceinline__ float fast_sigmoid(float t) {
    float e = __expf(-t);
    return __fdividef(1.0f, 1.0f + e);
}

// ---------- one 32->32 sine layer for 1 point, k packed in f32x2 pairs ----------
__device__ __forceinline__ void mid_layer(
    const float* __restrict__ sw,   // 32x32 row-major, prescaled by omega0
    const float* __restrict__ sb,   // 32, prescaled
    const float2* __restrict__ x,   // in: 16 packed k-pairs
    float2* __restrict__ y)         // out: 16 packed k-pairs
{
#pragma unroll
    for (int j = 0; j < 32; j++) {
        const float4* w4 = (const float4*)(sw + j * 32);
        float2 a = make_float2(sb[j], 0.0f);
#pragma unroll
        for (int m = 0; m < 8; m++) {
            float4 w = w4[m];
            a = ffma2(x[2 * m],     make_float2(w.x, w.y), a);
            a = ffma2(x[2 * m + 1], make_float2(w.z, w.w), a);
        }
        float s = fast_sin(a.x + a.y);
        if (j & 1) y[j >> 1].y = s;
        else       y[j >> 1].x = s;
    }
}

__global__ void __launch_bounds__(BLK, 2)
siren_kernel(const float* __restrict__ coords,
             const float* __restrict__ w0g, const float* __restrict__ b0g,
             const float* __restrict__ w1g, const float* __restrict__ b1g,
             const float* __restrict__ w2g, const float* __restrict__ b2g,
             const float* __restrict__ w3g, const float* __restrict__ b3g,
             const float* __restrict__ w4g, const float* __restrict__ b4g,
             const float* __restrict__ w5g, const float* __restrict__ b5g,
             const float* __restrict__ wfg, const float* __restrict__ bfg,
             float* __restrict__ out, int numPts)
{
    __shared__ __align__(16) float s_w0[64];
    __shared__              float s_b0[32];
    __shared__ __align__(16) float s_wm[4 * 1024];
    __shared__              float s_bm[4 * 32];
    __shared__ __align__(16) float s_w5[512];
    __shared__              float s_b5[16];
    __shared__ __align__(16) float s_wf[48];
    __shared__              float s_bf[3];

    const int t = threadIdx.x;
    for (int i = t; i < 64; i += BLK)  s_w0[i] = OMEGA0 * w0g[i];
    for (int i = t; i < 32; i += BLK)  s_b0[i] = OMEGA0 * b0g[i];
    {
        const float* wml[4] = { w1g, w2g, w3g, w4g };
        const float* bml[4] = { b1g, b2g, b3g, b4g };
#pragma unroll
        for (int l = 0; l < 4; l++) {
            for (int i = t; i < 1024; i += BLK) s_wm[l * 1024 + i] = OMEGA0 * wml[l][i];
            if (t < 32) s_bm[l * 32 + t] = OMEGA0 * bml[l][t];
        }
    }
    for (int i = t; i < 512; i += BLK) s_w5[i] = OMEGA0 * w5g[i];
    if (t < 16) s_b5[t] = OMEGA0 * b5g[t];
    if (t < 48) s_wf[t] = wfg[t];
    if (t < 3)  s_bf[t] = bfg[t];
    __syncthreads();

    const int base = blockIdx.x * (BLK * IT);

#pragma unroll 1
    for (int it = 0; it < IT; it++) {
        const int p = base + it * BLK + t;
        if (p >= numPts) break;

        // ---- load point ----
        float2 c = ((const float2*)coords)[p];

        float2 x[16], y[16];

        // ---- layer 0: 2 -> 32 ----
#pragma unroll
        for (int j = 0; j < 32; j++) {
            float2 w = ((const float2*)s_w0)[j];
            float2 a = make_float2(s_b0[j], 0.0f);
            a = ffma2(c, w, a);
            float s = fast_sin(a.x + a.y);
            if (j & 1) x[j >> 1].y = s;
            else       x[j >> 1].x = s;
        }

        // ---- 4 middle layers 32 -> 32 (ping-pong x <-> y) ----
        mid_layer(s_wm + 0 * 1024, s_bm + 0 * 32, x, y);
        mid_layer(s_wm + 1 * 1024, s_bm + 1 * 32, y, x);
        mid_layer(s_wm + 2 * 1024, s_bm + 2 * 32, x, y);
        mid_layer(s_wm + 3 * 1024, s_bm + 3 * 32, y, x);

        // ---- layer 5: 32 -> 16 ----
        float2 z[8];
#pragma unroll
        for (int j = 0; j < 16; j++) {
            const float4* w4 = (const float4*)(s_w5 + j * 32);
            float2 a = make_float2(s_b5[j], 0.0f);
#pragma unroll
            for (int m = 0; m < 8; m++) {
                float4 w = w4[m];
                a = ffma2(x[2 * m],     make_float2(w.x, w.y), a);
                a = ffma2(x[2 * m + 1], make_float2(w.z, w.w), a);
            }
            float s = fast_sin(a.x + a.y);
            if (j & 1) z[j >> 1].y = s;
            else       z[j >> 1].x = s;
        }

        // ---- final layer: 16 -> 3 + sigmoid ----
        float o[3];
#pragma unroll
        for (int cc = 0; cc < 3; cc++) {
            const float4* w4 = (const float4*)(s_wf + cc * 16);
            float2 a = make_float2(s_bf[cc], 0.0f);
#pragma unroll
            for (int m = 0; m < 4; m++) {
                float4 w = w4[m];
                a = ffma2(z[2 * m],     make_float2(w.x, w.y), a);
                a = ffma2(z[2 * m + 1], make_float2(w.z, w.w), a);
            }
            o[cc] = fast_sigmoid(a.x + a.y);
        }

        // ---- store 3 floats ----
        float* op = out + (size_t)p * 3;
        op[0] = o[0];
        op[1] = o[1];
        op[2] = o[2];
    }
}

extern "C" void kernel_launch(void* const* d_in, const int* in_sizes, int n_in,
                              void* d_out, int out_size)
{
    const float* coords = (const float*)d_in[0];
    const float* w0 = (const float*)d_in[1];  const float* b0 = (const float*)d_in[2];
    const float* w1 = (const float*)d_in[3];  const float* b1 = (const float*)d_in[4];
    const float* w2 = (const float*)d_in[5];  const float* b2 = (const float*)d_in[6];
    const float* w3 = (const float*)d_in[7];  const float* b3 = (const float*)d_in[8];
    const float* w4 = (const float*)d_in[9];  const float* b4 = (const float*)d_in[10];
    const float* w5 = (const float*)d_in[11]; const float* b5 = (const float*)d_in[12];
    const float* wf = (const float*)d_in[13]; const float* bf = (const float*)d_in[14];

    int numPts = in_sizes[0] / 2;                 // coords has N*2 floats
    int ptsPerBlock = BLK * IT;
    int grid = (numPts + ptsPerBlock - 1) / ptsPerBlock;

    siren_kernel<<<grid, BLK>>>(coords, w0, b0, w1, b1, w2, b2, w3, b3, w4, b4,
                                w5, b5, wf, bf, (float*)d_out, numPts);
}

// round 3
// speedup vs baseline: 1.7773x; 1.7773x over previous
#include <cuda_runtime.h>

#define OMEGA0 30.0f
#define BLK 128
#define IT 4   // pairs per thread

// ---------- packed f32x2 ops (sm_103a, only reachable via PTX) ----------
union F2u { float2 f; unsigned long long u; };

__device__ __forceinline__ float2 ffma2(float2 a, float2 b, float2 c) {
    F2u A, B, C, D;
    A.f = a; B.f = b; C.f = c;
    asm("fma.rn.f32x2 %0, %1, %2, %3;" : "=l"(D.u) : "l"(A.u), "l"(B.u), "l"(C.u));
    return D.f;
}
__device__ __forceinline__ float2 fadd2(float2 a, float2 b) {
    F2u A, B, D;
    A.f = a; B.f = b;
    asm("add.rn.f32x2 %0, %1, %2;" : "=l"(D.u) : "l"(A.u), "l"(B.u));
    return D.f;
}

// ---------- sine: fma-pipe-only range reduction + MUFU.SIN ----------
// magic-number round-to-nearest keeps us off the CVT pipe
__device__ __forceinline__ float fast_sin(float t) {
    const float MAGIC = 12582912.0f;               // 1.5 * 2^23
    float k = fmaf(t, 0.15915494309189535f, MAGIC);
    k -= MAGIC;
    t = fmaf(k, -6.2831855f, t);
    return __sinf(t);
}

__device__ __forceinline__ float fast_sigmoid(float t) {
    float e = __expf(-t);
    return __fdividef(1.0f, 1.0f + e);
}

// ---------- one 32->32 sine layer for 2 points ----------
// k packed in f32x2 pairs; even/odd m split into 2 chains per point (ILP 4)
__device__ __forceinline__ void mid_layer(
    const float* __restrict__ sw,   // 32x32 row-major, prescaled by omega0
    const float* __restrict__ sb,   // 32, prescaled
    const float2* __restrict__ xa, const float2* __restrict__ xb,
    float2* __restrict__ ya, float2* __restrict__ yb)
{
#pragma unroll 4
    for (int j = 0; j < 32; j++) {
        const float4* w4 = (const float4*)(sw + j * 32);
        float bj = sb[j];
        float2 e0 = make_float2(bj, 0.0f), o0 = make_float2(0.0f, 0.0f);
        float2 e1 = make_float2(bj, 0.0f), o1 = make_float2(0.0f, 0.0f);
#pragma unroll
        for (int m = 0; m < 8; m++) {
            float4 w = w4[m];
            float2 wlo = make_float2(w.x, w.y);
            float2 whi = make_float2(w.z, w.w);
            e0 = ffma2(xa[2 * m],     wlo, e0);
            o0 = ffma2(xa[2 * m + 1], whi, o0);
            e1 = ffma2(xb[2 * m],     wlo, e1);
            o1 = ffma2(xb[2 * m + 1], whi, o1);
        }
        float2 s0 = fadd2(e0, o0);
        float2 s1 = fadd2(e1, o1);
        float r0 = fast_sin(s0.x + s0.y);
        float r1 = fast_sin(s1.x + s1.y);
        if (j & 1) { ya[j >> 1].y = r0; yb[j >> 1].y = r1; }
        else       { ya[j >> 1].x = r0; yb[j >> 1].x = r1; }
    }
}

__global__ void __launch_bounds__(BLK, 3)
siren_kernel(const float* __restrict__ coords,
             const float* __restrict__ w0g, const float* __restrict__ b0g,
             const float* __restrict__ w1g, const float* __restrict__ b1g,
             const float* __restrict__ w2g, const float* __restrict__ b2g,
             const float* __restrict__ w3g, const float* __restrict__ b3g,
             const float* __restrict__ w4g, const float* __restrict__ b4g,
             const float* __restrict__ w5g, const float* __restrict__ b5g,
             const float* __restrict__ wfg, const float* __restrict__ bfg,
             float* __restrict__ out, int numPairs)
{
    __shared__ __align__(16) float s_w0[64];
    __shared__              float s_b0[32];
    __shared__ __align__(16) float s_wm[4 * 1024];
    __shared__              float s_bm[4 * 32];
    __shared__ __align__(16) float s_w5[512];
    __shared__              float s_b5[16];
    __shared__ __align__(16) float s_wf[48];
    __shared__              float s_bf[3];

    const int t = threadIdx.x;
    for (int i = t; i < 64; i += BLK)  s_w0[i] = OMEGA0 * w0g[i];
    if (t < 32) s_b0[t] = OMEGA0 * b0g[t];
    {
        const float* wml[4] = { w1g, w2g, w3g, w4g };
        const float* bml[4] = { b1g, b2g, b3g, b4g };
#pragma unroll
        for (int l = 0; l < 4; l++) {
            for (int i = t; i < 1024; i += BLK) s_wm[l * 1024 + i] = OMEGA0 * wml[l][i];
            if (t < 32) s_bm[l * 32 + t] = OMEGA0 * bml[l][t];
        }
    }
    for (int i = t; i < 512; i += BLK) s_w5[i] = OMEGA0 * w5g[i];
    if (t < 16) s_b5[t] = OMEGA0 * b5g[t];
    if (t < 48) s_wf[t] = wfg[t];
    if (t < 3)  s_bf[t] = bfg[t];
    __syncthreads();

    const int base = blockIdx.x * (BLK * IT);

#pragma unroll 1
    for (int it = 0; it < IT; it++) {
        const int pair = base + it * BLK + t;
        if (pair >= numPairs) break;

        // ---- load 2 points ----
        float4 c4 = ((const float4*)coords)[pair];
        float2 p0 = make_float2(c4.x, c4.y);
        float2 p1 = make_float2(c4.z, c4.w);

        float2 xa[16], xb[16], ya[16], yb[16];

        // ---- layer 0: 2 -> 32 ----
#pragma unroll 4
        for (int j = 0; j < 32; j++) {
            float2 w = ((const float2*)s_w0)[j];
            float2 a0 = make_float2(s_b0[j], 0.0f);
            float2 a1 = a0;
            a0 = ffma2(p0, w, a0);
            a1 = ffma2(p1, w, a1);
            float r0 = fast_sin(a0.x + a0.y);
            float r1 = fast_sin(a1.x + a1.y);
            if (j & 1) { xa[j >> 1].y = r0; xb[j >> 1].y = r1; }
            else       { xa[j >> 1].x = r0; xb[j >> 1].x = r1; }
        }

        // ---- 4 middle layers 32 -> 32 (ping-pong) ----
        mid_layer(s_wm + 0 * 1024, s_bm + 0 * 32, xa, xb, ya, yb);
        mid_layer(s_wm + 1 * 1024, s_bm + 1 * 32, ya, yb, xa, xb);
        mid_layer(s_wm + 2 * 1024, s_bm + 2 * 32, xa, xb, ya, yb);
        mid_layer(s_wm + 3 * 1024, s_bm + 3 * 32, ya, yb, xa, xb);

        // ---- layer 5: 32 -> 16 ----
        float2 za[8], zb[8];
#pragma unroll 4
        for (int j = 0; j < 16; j++) {
            const float4* w4 = (const float4*)(s_w5 + j * 32);
            float bj = s_b5[j];
            float2 e0 = make_float2(bj, 0.0f), o0 = make_float2(0.0f, 0.0f);
            float2 e1 = make_float2(bj, 0.0f), o1 = make_float2(0.0f, 0.0f);
#pragma unroll
            for (int m = 0; m < 8; m++) {
                float4 w = w4[m];
                float2 wlo = make_float2(w.x, w.y);
                float2 whi = make_float2(w.z, w.w);
                e0 = ffma2(xa[2 * m],     wlo, e0);
                o0 = ffma2(xa[2 * m + 1], whi, o0);
                e1 = ffma2(xb[2 * m],     wlo, e1);
                o1 = ffma2(xb[2 * m + 1], whi, o1);
            }
            float2 s0 = fadd2(e0, o0);
            float2 s1 = fadd2(e1, o1);
            float r0 = fast_sin(s0.x + s0.y);
            float r1 = fast_sin(s1.x + s1.y);
            if (j & 1) { za[j >> 1].y = r0; zb[j >> 1].y = r1; }
            else       { za[j >> 1].x = r0; zb[j >> 1].x = r1; }
        }

        // ---- final layer: 16 -> 3 + sigmoid ----
        float o0v[3], o1v[3];
#pragma unroll
        for (int cc = 0; cc < 3; cc++) {
            const float4* w4 = (const float4*)(s_wf + cc * 16);
            float2 a0 = make_float2(s_bf[cc], 0.0f);
            float2 a1 = a0;
#pragma unroll
            for (int m = 0; m < 4; m++) {
                float4 w = w4[m];
                float2 wlo = make_float2(w.x, w.y);
                float2 whi = make_float2(w.z, w.w);
                a0 = ffma2(za[2 * m],     wlo, a0);
                a0 = ffma2(za[2 * m + 1], whi, a0);
                a1 = ffma2(zb[2 * m],     wlo, a1);
                a1 = ffma2(zb[2 * m + 1], whi, a1);
            }
            o0v[cc] = fast_sigmoid(a0.x + a0.y);
            o1v[cc] = fast_sigmoid(a1.x + a1.y);
        }

        // ---- store 6 floats (2 points x RGB) as 3x STG.64 ----
        float2* op = (float2*)(out + (size_t)pair * 6);
        op[0] = make_float2(o0v[0], o0v[1]);
        op[1] = make_float2(o0v[2], o1v[0]);
        op[2] = make_float2(o1v[1], o1v[2]);
    }
}

extern "C" void kernel_launch(void* const* d_in, const int* in_sizes, int n_in,
                              void* d_out, int out_size)
{
    const float* coords = (const float*)d_in[0];
    const float* w0 = (const float*)d_in[1];  const float* b0 = (const float*)d_in[2];
    const float* w1 = (const float*)d_in[3];  const float* b1 = (const float*)d_in[4];
    const float* w2 = (const float*)d_in[5];  const float* b2 = (const float*)d_in[6];
    const float* w3 = (const float*)d_in[7];  const float* b3 = (const float*)d_in[8];
    const float* w4 = (const float*)d_in[9];  const float* b4 = (const float*)d_in[10];
    const float* w5 = (const float*)d_in[11]; const float* b5 = (const float*)d_in[12];
    const float* wf = (const float*)d_in[13]; const float* bf = (const float*)d_in[14];

    int numPairs = in_sizes[0] / 4;   // coords has N*2 floats, 2 points per pair
    int pairsPerBlock = BLK * IT;
    int grid = (numPairs + pairsPerBlock - 1) / pairsPerBlock;

    siren_kernel<<<grid, BLK>>>(coords, w0, b0, w1, b1, w2, b2, w3, b3, w4, b4,
                                w5, b5, wf, bf, (float*)d_out, numPairs);
}

// round 5
// speedup vs baseline: 4.2212x; 2.3750x over previous
#include <cuda_runtime.h>
#include <cuda_bf16.h>
#include <cstdint>

#define OMEGA0 30.0f
#define BLK 128
#define GRID 1024

// ---------------- helpers ----------------
__device__ __forceinline__ float fast_sin(float t) {
    const float MAGIC = 12582912.0f;                 // 1.5 * 2^23
    float k = fmaf(t, 0.15915494309189535f, MAGIC);
    k -= MAGIC;
    t = fmaf(k, -6.2831855f, t);
    return __sinf(t);
}
__device__ __forceinline__ float fast_sigmoid(float t) {
    return __fdividef(1.0f, 1.0f + __expf(-t));
}
// pack two f32 -> bf16x2 (x in low half, y in high half)
__device__ __forceinline__ uint32_t pack_bf16x2(float x, float y) {
    uint32_t r;
    asm("cvt.rn.bf16x2.f32 %0, %1, %2;" : "=r"(r) : "f"(y), "f"(x));
    return r;
}
// split (x,y) into packed bf16x2 hi and packed bf16x2 residual lo
__device__ __forceinline__ void split_pair(float x, float y, uint32_t& h, uint32_t& l) {
    h = pack_bf16x2(x, y);
    float hx = __uint_as_float(h << 16);
    float hy = __uint_as_float(h & 0xFFFF0000u);
    l = pack_bf16x2(x - hx, y - hy);
}
// D += A * B   (m16n8k16, bf16 in, f32 accum)
__device__ __forceinline__ void mma_bf16(float d[4], const uint32_t a[4],
                                         uint32_t b0, uint32_t b1) {
    asm volatile(
        "mma.sync.aligned.m16n8k16.row.col.f32.bf16.bf16.f32 "
        "{%0,%1,%2,%3}, {%4,%5,%6,%7}, {%8,%9}, {%0,%1,%2,%3};"
        : "+f"(d[0]), "+f"(d[1]), "+f"(d[2]), "+f"(d[3])
        : "r"(a[0]), "r"(a[1]), "r"(a[2]), "r"(a[3]), "r"(b0), "r"(b1));
}

// Build A fragments (hi & lo) for k=32 from 4 n-tiles of fp32 values in D layout.
// v[nt][i]: i=0:(row g,col 2t) 1:(g,2t+1) 2:(g+8,2t) 3:(g+8,2t+1), cols nt*8+...
// A frag for ktile kt: regs {(g,2t),(g+8,2t)half? } per PTX m16n8k16 row-major A:
//   ra0=(row g, k 2t/2t+1) ra1=(row g+8, same) ra2=(row g, k 2t+8/+9) ra3=(row g+8, same)
// k = kt*16 + {2t..} -> first half from ntile 2kt, second half from ntile 2kt+1.
#define BUILD_A(vsrc, Ah, Al) do {                                              \
    _Pragma("unroll")                                                           \
    for (int mt_ = 0; mt_ < 2; mt_++) {                                         \
        _Pragma("unroll")                                                       \
        for (int kt_ = 0; kt_ < 2; kt_++) {                                     \
            split_pair(vsrc[mt_][2*kt_][0],   vsrc[mt_][2*kt_][1],              \
                       Ah[mt_][kt_][0], Al[mt_][kt_][0]);                       \
            split_pair(vsrc[mt_][2*kt_][2],   vsrc[mt_][2*kt_][3],              \
                       Ah[mt_][kt_][1], Al[mt_][kt_][1]);                       \
            split_pair(vsrc[mt_][2*kt_+1][0], vsrc[mt_][2*kt_+1][1],            \
                       Ah[mt_][kt_][2], Al[mt_][kt_][2]);                       \
            split_pair(vsrc[mt_][2*kt_+1][2], vsrc[mt_][2*kt_+1][3],            \
                       Ah[mt_][kt_][3], Al[mt_][kt_][3]);                       \
        }                                                                       \
    }                                                                           \
} while (0)

__global__ void __launch_bounds__(BLK, 4)
siren_hmma(const float* __restrict__ coords,
           const float* __restrict__ w0g, const float* __restrict__ b0g,
           const float* __restrict__ w1g, const float* __restrict__ b1g,
           const float* __restrict__ w2g, const float* __restrict__ b2g,
           const float* __restrict__ w3g, const float* __restrict__ b3g,
           const float* __restrict__ w4g, const float* __restrict__ b4g,
           const float* __restrict__ w5g, const float* __restrict__ b5g,
           const float* __restrict__ wfg, const float* __restrict__ bfg,
           float* __restrict__ out, int numPts, int numTiles)
{
    // per-lane pre-swizzled B fragments: frag[q*32 + lane]
    // mid layers: q = kt*8 + r*4 + nt  (kt<2, r<2, nt<4) -> 16 regs/warp
    __shared__ uint32_t fragH[4][512], fragL[4][512];
    // layer 5: q = kt*4 + r*2 + nt (nt<2) -> 8 regs/warp
    __shared__ uint32_t fragH5[256], fragL5[256];
    __shared__ float2 biasM[4][16];   // [layer][nt*4+t]: (b[8nt+2t], b[8nt+2t+1])
    __shared__ float2 bias5[8];
    __shared__ float s_w0[64], s_b0[32], s_wf[48], s_bf[3];

    const int tid = threadIdx.x;
    const int lane = tid & 31, wid = tid >> 5;
    const int t4 = lane & 3, g = lane >> 2;

    // ---- fill weight fragments (per-lane order, conflict-free at use) ----
#define FILL_MID(Lc, WP)                                                       \
    for (int e = tid; e < 512; e += BLK) {                                     \
        int q = e >> 5, ln = e & 31;                                           \
        int tt = ln & 3, gg = ln >> 2;                                         \
        int kt = q >> 3, r = (q >> 2) & 1, nt = q & 3;                         \
        int k0 = kt * 16 + r * 8 + tt * 2;                                     \
        int n  = nt * 8 + gg;                                                  \
        float v0 = OMEGA0 * WP[n * 32 + k0];                                   \
        float v1 = OMEGA0 * WP[n * 32 + k0 + 1];                               \
        uint32_t h_, l_; split_pair(v0, v1, h_, l_);                           \
        fragH[Lc][e] = h_; fragL[Lc][e] = l_;                                  \
    }
    FILL_MID(0, w1g) FILL_MID(1, w2g) FILL_MID(2, w3g) FILL_MID(3, w4g)
#undef FILL_MID

    for (int e = tid; e < 256; e += BLK) {
        int q = e >> 5, ln = e & 31;
        int tt = ln & 3, gg = ln >> 2;
        int kt = q >> 2, r = (q >> 1) & 1, nt = q & 1;
        int k0 = kt * 16 + r * 8 + tt * 2;
        int n  = nt * 8 + gg;
        float v0 = OMEGA0 * w5g[n * 32 + k0];
        float v1 = OMEGA0 * w5g[n * 32 + k0 + 1];
        uint32_t h_, l_; split_pair(v0, v1, h_, l_);
        fragH5[e] = h_; fragL5[e] = l_;
    }
#define FILL_BIAS(Lc, BP)                                                      \
    if (tid < 16) {                                                            \
        int nt = tid >> 2, tt = tid & 3;                                       \
        biasM[Lc][tid] = make_float2(OMEGA0 * BP[nt * 8 + tt * 2],             \
                                     OMEGA0 * BP[nt * 8 + tt * 2 + 1]);        \
    }
    FILL_BIAS(0, b1g) FILL_BIAS(1, b2g) FILL_BIAS(2, b3g) FILL_BIAS(3, b4g)
#undef FILL_BIAS
    if (tid < 8) {
        int nt = tid >> 2, tt = tid & 3;
        bias5[tid] = make_float2(OMEGA0 * b5g[nt * 8 + tt * 2],
                                 OMEGA0 * b5g[nt * 8 + tt * 2 + 1]);
    }
    if (tid < 64) s_w0[tid] = OMEGA0 * w0g[tid];
    if (tid < 32) s_b0[tid] = OMEGA0 * b0g[tid];
    if (tid < 48) s_wf[tid] = wfg[tid];
    if (tid < 3)  s_bf[tid] = bfg[tid];
    __syncthreads();

    // ---------------- main loop: 128 points per CTA-iter (32 per warp) ----------------
#pragma unroll 1
    for (int tile = blockIdx.x; tile < numTiles; tile += gridDim.x) {
        const int pbase = tile * 128 + wid * 32;

        // activation state in D-fragment layout: v[mtile][ntile][c0..c3]
        float v[2][4][4];

        // ---- layer 0: 2 -> 32, computed directly into fragment layout ----
#pragma unroll
        for (int mt = 0; mt < 2; mt++) {
            int p0 = pbase + mt * 16 + g;
            float2 c0 = (p0 < numPts)     ? ((const float2*)coords)[p0]     : make_float2(0.f, 0.f);
            float2 c1 = (p0 + 8 < numPts) ? ((const float2*)coords)[p0 + 8] : make_float2(0.f, 0.f);
#pragma unroll
            for (int nt = 0; nt < 4; nt++) {
                int col = nt * 8 + t4 * 2;
                float2 wa = ((const float2*)s_w0)[col];
                float2 wb = ((const float2*)s_w0)[col + 1];
                float ba = s_b0[col], bb_ = s_b0[col + 1];
                v[mt][nt][0] = fast_sin(fmaf(c0.x, wa.x, fmaf(c0.y, wa.y, ba)));
                v[mt][nt][1] = fast_sin(fmaf(c0.x, wb.x, fmaf(c0.y, wb.y, bb_)));
                v[mt][nt][2] = fast_sin(fmaf(c1.x, wa.x, fmaf(c1.y, wa.y, ba)));
                v[mt][nt][3] = fast_sin(fmaf(c1.x, wb.x, fmaf(c1.y, wb.y, bb_)));
            }
        }

        // ---- 4 middle layers 32 -> 32 on HMMA ----
#pragma unroll 1
        for (int L = 0; L < 4; L++) {
            uint32_t Ah[2][2][4], Al[2][2][4];
            BUILD_A(v, Ah, Al);

            uint32_t B[16];
#pragma unroll
            for (int q = 0; q < 16; q++) B[q] = fragH[L][q * 32 + lane];

            // init accumulators with bias
#pragma unroll
            for (int nt = 0; nt < 4; nt++) {
                float2 bb = biasM[L][nt * 4 + t4];
#pragma unroll
                for (int mt = 0; mt < 2; mt++) {
                    v[mt][nt][0] = bb.x; v[mt][nt][1] = bb.y;
                    v[mt][nt][2] = bb.x; v[mt][nt][3] = bb.y;
                }
            }
            // x_hi*W_hi + x_lo*W_hi
#pragma unroll
            for (int mt = 0; mt < 2; mt++)
#pragma unroll
                for (int nt = 0; nt < 4; nt++)
#pragma unroll
                    for (int kt = 0; kt < 2; kt++) {
                        mma_bf16(v[mt][nt], Ah[mt][kt], B[kt * 8 + nt], B[kt * 8 + 4 + nt]);
                        mma_bf16(v[mt][nt], Al[mt][kt], B[kt * 8 + nt], B[kt * 8 + 4 + nt]);
                    }
            // x_hi*W_lo
#pragma unroll
            for (int q = 0; q < 16; q++) B[q] = fragL[L][q * 32 + lane];
#pragma unroll
            for (int mt = 0; mt < 2; mt++)
#pragma unroll
                for (int nt = 0; nt < 4; nt++)
#pragma unroll
                    for (int kt = 0; kt < 2; kt++)
                        mma_bf16(v[mt][nt], Ah[mt][kt], B[kt * 8 + nt], B[kt * 8 + 4 + nt]);
            // sine
#pragma unroll
            for (int mt = 0; mt < 2; mt++)
#pragma unroll
                for (int nt = 0; nt < 4; nt++)
#pragma unroll
                    for (int i = 0; i < 4; i++)
                        v[mt][nt][i] = fast_sin(v[mt][nt][i]);
        }

        // ---- layer 5: 32 -> 16 on HMMA (outputs in ntiles 0,1 of v) ----
        {
            uint32_t Ah[2][2][4], Al[2][2][4];
            BUILD_A(v, Ah, Al);

            uint32_t B5[8];
#pragma unroll
            for (int q = 0; q < 8; q++) B5[q] = fragH5[q * 32 + lane];
#pragma unroll
            for (int nt = 0; nt < 2; nt++) {
                float2 bb = bias5[nt * 4 + t4];
#pragma unroll
                for (int mt = 0; mt < 2; mt++) {
                    v[mt][nt][0] = bb.x; v[mt][nt][1] = bb.y;
                    v[mt][nt][2] = bb.x; v[mt][nt][3] = bb.y;
                }
            }
#pragma unroll
            for (int mt = 0; mt < 2; mt++)
#pragma unroll
                for (int nt = 0; nt < 2; nt++)
#pragma unroll
                    for (int kt = 0; kt < 2; kt++) {
                        mma_bf16(v[mt][nt], Ah[mt][kt], B5[kt * 4 + nt], B5[kt * 4 + 2 + nt]);
                        mma_bf16(v[mt][nt], Al[mt][kt], B5[kt * 4 + nt], B5[kt * 4 + 2 + nt]);
                    }
#pragma unroll
            for (int q = 0; q < 8; q++) B5[q] = fragL5[q * 32 + lane];
#pragma unroll
            for (int mt = 0; mt < 2; mt++)
#pragma unroll
                for (int nt = 0; nt < 2; nt++)
#pragma unroll
                    for (int kt = 0; kt < 2; kt++)
                        mma_bf16(v[mt][nt], Ah[mt][kt], B5[kt * 4 + nt], B5[kt * 4 + 2 + nt]);
#pragma unroll
            for (int mt = 0; mt < 2; mt++)
#pragma unroll
                for (int nt = 0; nt < 2; nt++)
#pragma unroll
                    for (int i = 0; i < 4; i++)
                        v[mt][nt][i] = fast_sin(v[mt][nt][i]);
        }

        // ---- final 16 -> 3 + sigmoid: per-lane partials + 4-lane butterfly reduce ----
#pragma unroll
        for (int mt = 0; mt < 2; mt++) {
            float s[2][3];
#pragma unroll
            for (int c = 0; c < 3; c++) {
                float2 wa = ((const float2*)s_wf)[c * 8 + t4];       // cols 2t,2t+1
                float2 wb = ((const float2*)s_wf)[c * 8 + 4 + t4];   // cols 8+2t,9+2t
#pragma unroll
                for (int r = 0; r < 2; r++) {
                    float acc = v[mt][0][2 * r]     * wa.x
                              + v[mt][0][2 * r + 1] * wa.y
                              + v[mt][1][2 * r]     * wb.x
                              + v[mt][1][2 * r + 1] * wb.y;
                    acc += __shfl_xor_sync(0xffffffffu, acc, 1);
                    acc += __shfl_xor_sync(0xffffffffu, acc, 2);
                    s[r][c] = acc + s_bf[c];
                }
            }
            if (t4 < 3) {
#pragma unroll
                for (int r = 0; r < 2; r++) {
                    int p = pbase + mt * 16 + g + 8 * r;
                    if (p < numPts) {
                        float val = (t4 == 0) ? s[r][0] : ((t4 == 1) ? s[r][1] : s[r][2]);
                        out[(size_t)p * 3 + t4] = fast_sigmoid(val);
                    }
                }
            }
        }
    }
}

extern "C" void kernel_launch(void* const* d_in, const int* in_sizes, int n_in,
                              void* d_out, int out_size)
{
    const float* coords = (const float*)d_in[0];
    const float* w0 = (const float*)d_in[1];  const float* b0 = (const float*)d_in[2];
    const float* w1 = (const float*)d_in[3];  const float* b1 = (const float*)d_in[4];
    const float* w2 = (const float*)d_in[5];  const float* b2 = (const float*)d_in[6];
    const float* w3 = (const float*)d_in[7];  const float* b3 = (const float*)d_in[8];
    const float* w4 = (const float*)d_in[9];  const float* b4 = (const float*)d_in[10];
    const float* w5 = (const float*)d_in[11]; const float* b5 = (const float*)d_in[12];
    const float* wf = (const float*)d_in[13]; const float* bf = (const float*)d_in[14];

    int numPts = in_sizes[0] / 2;
    int numTiles = (numPts + 127) / 128;
    int grid = numTiles < GRID ? numTiles : GRID;

    siren_hmma<<<grid, BLK>>>(coords, w0, b0, w1, b1, w2, b2, w3, b3, w4, b4,
                              w5, b5, wf, bf, (float*)d_out, numPts, numTiles);
}

// round 6
// speedup vs baseline: 4.5441x; 1.0765x over previous
#include <cuda_runtime.h>
#include <cuda_bf16.h>
#include <cstdint>

#define OMEGA0 30.0f
#define BLK 128
#define MAXCTAS 740   // 148 SMs x 5 CTAs

// ---------------- helpers ----------------
__device__ __forceinline__ float fast_sigmoid(float t) {
    return __fdividef(1.0f, 1.0f + __expf(-t));
}
// pack two f32 -> bf16x2 (x in low half, y in high half)
__device__ __forceinline__ uint32_t pack_bf16x2(float x, float y) {
    uint32_t r;
    asm("cvt.rn.bf16x2.f32 %0, %1, %2;" : "=r"(r) : "f"(y), "f"(x));
    return r;
}
// split (x,y) into packed bf16x2 hi and packed bf16x2 residual lo
__device__ __forceinline__ void split_pair(float x, float y, uint32_t& h, uint32_t& l) {
    h = pack_bf16x2(x, y);
    float hx = __uint_as_float(h << 16);
    float hy = __uint_as_float(h & 0xFFFF0000u);
    l = pack_bf16x2(x - hx, y - hy);
}
// D += A * B   (m16n8k16, bf16 in, f32 accum)
__device__ __forceinline__ void mma_bf16(float d[4], const uint32_t a[4],
                                         uint32_t b0, uint32_t b1) {
    asm volatile(
        "mma.sync.aligned.m16n8k16.row.col.f32.bf16.bf16.f32 "
        "{%0,%1,%2,%3}, {%4,%5,%6,%7}, {%8,%9}, {%0,%1,%2,%3};"
        : "+f"(d[0]), "+f"(d[1]), "+f"(d[2]), "+f"(d[3])
        : "r"(a[0]), "r"(a[1]), "r"(a[2]), "r"(a[3]), "r"(b0), "r"(b1));
}

// Build A fragments (hi & lo) for k=32 from 4 n-tiles of fp32 values in D layout.
#define BUILD_A(vsrc, Ah, Al) do {                                              \
    _Pragma("unroll")                                                           \
    for (int mt_ = 0; mt_ < 2; mt_++) {                                         \
        _Pragma("unroll")                                                       \
        for (int kt_ = 0; kt_ < 2; kt_++) {                                     \
            split_pair(vsrc[mt_][2*kt_][0],   vsrc[mt_][2*kt_][1],              \
                       Ah[mt_][kt_][0], Al[mt_][kt_][0]);                       \
            split_pair(vsrc[mt_][2*kt_][2],   vsrc[mt_][2*kt_][3],              \
                       Ah[mt_][kt_][1], Al[mt_][kt_][1]);                       \
            split_pair(vsrc[mt_][2*kt_+1][0], vsrc[mt_][2*kt_+1][1],            \
                       Ah[mt_][kt_][2], Al[mt_][kt_][2]);                       \
            split_pair(vsrc[mt_][2*kt_+1][2], vsrc[mt_][2*kt_+1][3],            \
                       Ah[mt_][kt_][3], Al[mt_][kt_][3]);                       \
        }                                                                       \
    }                                                                           \
} while (0)

// Fragment smem layout: per-lane contiguous, 36-word lane stride (144B).
// hi q at [lane][q] (q<16), lo q at [lane][16+q], pad 4 words.
// 144B stride => LDS.128 bank offsets 4*l mod 32 within each 8-lane phase:
// conflict-free 4-phase minimum.

__global__ void __launch_bounds__(BLK, 5)
siren_hmma(const float* __restrict__ coords,
           const float* __restrict__ w0g, const float* __restrict__ b0g,
           const float* __restrict__ w1g, const float* __restrict__ b1g,
           const float* __restrict__ w2g, const float* __restrict__ b2g,
           const float* __restrict__ w3g, const float* __restrict__ b3g,
           const float* __restrict__ w4g, const float* __restrict__ b4g,
           const float* __restrict__ w5g, const float* __restrict__ b5g,
           const float* __restrict__ wfg, const float* __restrict__ bfg,
           float* __restrict__ out, int numPts, int numTiles)
{
    __shared__ __align__(16) uint32_t fragMid[4][32][36];
    __shared__ __align__(16) uint32_t frag5[32][36];
    __shared__ float2 biasM[4][16];   // [layer][nt*4+t]
    __shared__ float2 bias5[8];
    __shared__ float s_w0[64], s_b0[32], s_wf[48], s_bf[3];

    const int tid = threadIdx.x;
    const int lane = tid & 31, wid = tid >> 5;
    const int t4 = lane & 3, g = lane >> 2;

    // ---- fill weight fragments ----
#define FILL_MID(Lc, WP)                                                       \
    for (int e = tid; e < 512; e += BLK) {                                     \
        int q = e >> 5, ln = e & 31;                                           \
        int tt = ln & 3, gg = ln >> 2;                                         \
        int kt = q >> 3, r = (q >> 2) & 1, nt = q & 3;                         \
        int k0 = kt * 16 + r * 8 + tt * 2;                                     \
        int n  = nt * 8 + gg;                                                  \
        float v0 = OMEGA0 * WP[n * 32 + k0];                                   \
        float v1 = OMEGA0 * WP[n * 32 + k0 + 1];                               \
        uint32_t h_, l_; split_pair(v0, v1, h_, l_);                           \
        fragMid[Lc][ln][q] = h_; fragMid[Lc][ln][16 + q] = l_;                 \
    }
    FILL_MID(0, w1g) FILL_MID(1, w2g) FILL_MID(2, w3g) FILL_MID(3, w4g)
#undef FILL_MID

    for (int e = tid; e < 256; e += BLK) {
        int q = e >> 5, ln = e & 31;
        int tt = ln & 3, gg = ln >> 2;
        int kt = q >> 2, r = (q >> 1) & 1, nt = q & 1;
        int k0 = kt * 16 + r * 8 + tt * 2;
        int n  = nt * 8 + gg;
        float v0 = OMEGA0 * w5g[n * 32 + k0];
        float v1 = OMEGA0 * w5g[n * 32 + k0 + 1];
        uint32_t h_, l_; split_pair(v0, v1, h_, l_);
        frag5[ln][q] = h_; frag5[ln][16 + q] = l_;
    }
#define FILL_BIAS(Lc, BP)                                                      \
    if (tid < 16) {                                                            \
        int nt = tid >> 2, tt = tid & 3;                                       \
        biasM[Lc][tid] = make_float2(OMEGA0 * BP[nt * 8 + tt * 2],             \
                                     OMEGA0 * BP[nt * 8 + tt * 2 + 1]);        \
    }
    FILL_BIAS(0, b1g) FILL_BIAS(1, b2g) FILL_BIAS(2, b3g) FILL_BIAS(3, b4g)
#undef FILL_BIAS
    if (tid < 8) {
        int nt = tid >> 2, tt = tid & 3;
        bias5[tid] = make_float2(OMEGA0 * b5g[nt * 8 + tt * 2],
                                 OMEGA0 * b5g[nt * 8 + tt * 2 + 1]);
    }
    if (tid < 64) s_w0[tid] = OMEGA0 * w0g[tid];
    if (tid < 32) s_b0[tid] = OMEGA0 * b0g[tid];
    if (tid < 48) s_wf[tid] = wfg[tid];
    if (tid < 3)  s_bf[tid] = bfg[tid];
    __syncthreads();

    // ---------------- main loop: 128 points per CTA-iter (32 per warp) ----------------
#pragma unroll 1
    for (int tile = blockIdx.x; tile < numTiles; tile += gridDim.x) {
        const int pbase = tile * 128 + wid * 32;

        // activation state in D-fragment layout: v[mtile][ntile][c0..c3]
        float v[2][4][4];

        // ---- layer 0: 2 -> 32, direct to fragment layout ----
#pragma unroll
        for (int mt = 0; mt < 2; mt++) {
            int p0 = pbase + mt * 16 + g;
            float2 c0 = (p0 < numPts)     ? ((const float2*)coords)[p0]     : make_float2(0.f, 0.f);
            float2 c1 = (p0 + 8 < numPts) ? ((const float2*)coords)[p0 + 8] : make_float2(0.f, 0.f);
#pragma unroll
            for (int nt = 0; nt < 4; nt++) {
                int col = nt * 8 + t4 * 2;
                float2 wa = ((const float2*)s_w0)[col];
                float2 wb = ((const float2*)s_w0)[col + 1];
                float ba = s_b0[col], bb_ = s_b0[col + 1];
                v[mt][nt][0] = __sinf(fmaf(c0.x, wa.x, fmaf(c0.y, wa.y, ba)));
                v[mt][nt][1] = __sinf(fmaf(c0.x, wb.x, fmaf(c0.y, wb.y, bb_)));
                v[mt][nt][2] = __sinf(fmaf(c1.x, wa.x, fmaf(c1.y, wa.y, ba)));
                v[mt][nt][3] = __sinf(fmaf(c1.x, wb.x, fmaf(c1.y, wb.y, bb_)));
            }
        }

        // ---- 4 middle layers 32 -> 32 on HMMA ----
#pragma unroll 1
        for (int L = 0; L < 4; L++) {
            uint32_t Ah[2][2][4], Al[2][2][4];
            BUILD_A(v, Ah, Al);

            const uint4* bph = (const uint4*)&fragMid[L][lane][0];
            uint32_t B[16];
            {
                uint4 b0_ = bph[0], b1_ = bph[1], b2_ = bph[2], b3_ = bph[3];
                B[0]=b0_.x; B[1]=b0_.y; B[2]=b0_.z; B[3]=b0_.w;
                B[4]=b1_.x; B[5]=b1_.y; B[6]=b1_.z; B[7]=b1_.w;
                B[8]=b2_.x; B[9]=b2_.y; B[10]=b2_.z; B[11]=b2_.w;
                B[12]=b3_.x; B[13]=b3_.y; B[14]=b3_.z; B[15]=b3_.w;
            }

            // init accumulators with bias
#pragma unroll
            for (int nt = 0; nt < 4; nt++) {
                float2 bb = biasM[L][nt * 4 + t4];
#pragma unroll
                for (int mt = 0; mt < 2; mt++) {
                    v[mt][nt][0] = bb.x; v[mt][nt][1] = bb.y;
                    v[mt][nt][2] = bb.x; v[mt][nt][3] = bb.y;
                }
            }
            // x_hi*W_hi + x_lo*W_hi
#pragma unroll
            for (int mt = 0; mt < 2; mt++)
#pragma unroll
                for (int nt = 0; nt < 4; nt++)
#pragma unroll
                    for (int kt = 0; kt < 2; kt++) {
                        mma_bf16(v[mt][nt], Ah[mt][kt], B[kt * 8 + nt], B[kt * 8 + 4 + nt]);
                        mma_bf16(v[mt][nt], Al[mt][kt], B[kt * 8 + nt], B[kt * 8 + 4 + nt]);
                    }
            // x_hi*W_lo
            {
                const uint4* bpl = (const uint4*)&fragMid[L][lane][16];
                uint4 b0_ = bpl[0], b1_ = bpl[1], b2_ = bpl[2], b3_ = bpl[3];
                B[0]=b0_.x; B[1]=b0_.y; B[2]=b0_.z; B[3]=b0_.w;
                B[4]=b1_.x; B[5]=b1_.y; B[6]=b1_.z; B[7]=b1_.w;
                B[8]=b2_.x; B[9]=b2_.y; B[10]=b2_.z; B[11]=b2_.w;
                B[12]=b3_.x; B[13]=b3_.y; B[14]=b3_.z; B[15]=b3_.w;
            }
#pragma unroll
            for (int mt = 0; mt < 2; mt++)
#pragma unroll
                for (int nt = 0; nt < 4; nt++)
#pragma unroll
                    for (int kt = 0; kt < 2; kt++)
                        mma_bf16(v[mt][nt], Ah[mt][kt], B[kt * 8 + nt], B[kt * 8 + 4 + nt]);
            // sine (raw MUFU.SIN — HW handles range; |pre-act| ~ O(1..10))
#pragma unroll
            for (int mt = 0; mt < 2; mt++)
#pragma unroll
                for (int nt = 0; nt < 4; nt++)
#pragma unroll
                    for (int i = 0; i < 4; i++)
                        v[mt][nt][i] = __sinf(v[mt][nt][i]);
        }

        // ---- layer 5: 32 -> 16 on HMMA ----
        {
            uint32_t Ah[2][2][4], Al[2][2][4];
            BUILD_A(v, Ah, Al);

            uint32_t B5[8];
            {
                const uint4* bph = (const uint4*)&frag5[lane][0];
                uint4 b0_ = bph[0], b1_ = bph[1];
                B5[0]=b0_.x; B5[1]=b0_.y; B5[2]=b0_.z; B5[3]=b0_.w;
                B5[4]=b1_.x; B5[5]=b1_.y; B5[6]=b1_.z; B5[7]=b1_.w;
            }
#pragma unroll
            for (int nt = 0; nt < 2; nt++) {
                float2 bb = bias5[nt * 4 + t4];
#pragma unroll
                for (int mt = 0; mt < 2; mt++) {
                    v[mt][nt][0] = bb.x; v[mt][nt][1] = bb.y;
                    v[mt][nt][2] = bb.x; v[mt][nt][3] = bb.y;
                }
            }
#pragma unroll
            for (int mt = 0; mt < 2; mt++)
#pragma unroll
                for (int nt = 0; nt < 2; nt++)
#pragma unroll
                    for (int kt = 0; kt < 2; kt++) {
                        mma_bf16(v[mt][nt], Ah[mt][kt], B5[kt * 4 + nt], B5[kt * 4 + 2 + nt]);
                        mma_bf16(v[mt][nt], Al[mt][kt], B5[kt * 4 + nt], B5[kt * 4 + 2 + nt]);
                    }
            {
                const uint4* bpl = (const uint4*)&frag5[lane][16];
                uint4 b0_ = bpl[0], b1_ = bpl[1];
                B5[0]=b0_.x; B5[1]=b0_.y; B5[2]=b0_.z; B5[3]=b0_.w;
                B5[4]=b1_.x; B5[5]=b1_.y; B5[6]=b1_.z; B5[7]=b1_.w;
            }
#pragma unroll
            for (int mt = 0; mt < 2; mt++)
#pragma unroll
                for (int nt = 0; nt < 2; nt++)
#pragma unroll
                    for (int kt = 0; kt < 2; kt++)
                        mma_bf16(v[mt][nt], Ah[mt][kt], B5[kt * 4 + nt], B5[kt * 4 + 2 + nt]);
#pragma unroll
            for (int mt = 0; mt < 2; mt++)
#pragma unroll
                for (int nt = 0; nt < 2; nt++)
#pragma unroll
                    for (int i = 0; i < 4; i++)
                        v[mt][nt][i] = __sinf(v[mt][nt][i]);
        }

        // ---- final 16 -> 3 + sigmoid: per-lane partials + 4-lane butterfly reduce ----
#pragma unroll
        for (int mt = 0; mt < 2; mt++) {
            float s[2][3];
#pragma unroll
            for (int c = 0; c < 3; c++) {
                float2 wa = ((const float2*)s_wf)[c * 8 + t4];
                float2 wb = ((const float2*)s_wf)[c * 8 + 4 + t4];
#pragma unroll
                for (int r = 0; r < 2; r++) {
                    float acc = v[mt][0][2 * r]     * wa.x
                              + v[mt][0][2 * r + 1] * wa.y
                              + v[mt][1][2 * r]     * wb.x
                              + v[mt][1][2 * r + 1] * wb.y;
                    acc += __shfl_xor_sync(0xffffffffu, acc, 1);
                    acc += __shfl_xor_sync(0xffffffffu, acc, 2);
                    s[r][c] = acc + s_bf[c];
                }
            }
            if (t4 < 3) {
#pragma unroll
                for (int r = 0; r < 2; r++) {
                    int p = pbase + mt * 16 + g + 8 * r;
                    if (p < numPts) {
                        float val = (t4 == 0) ? s[r][0] : ((t4 == 1) ? s[r][1] : s[r][2]);
                        out[(size_t)p * 3 + t4] = fast_sigmoid(val);
                    }
                }
            }
        }
    }
}

extern "C" void kernel_launch(void* const* d_in, const int* in_sizes, int n_in,
                              void* d_out, int out_size)
{
    const float* coords = (const float*)d_in[0];
    const float* w0 = (const float*)d_in[1];  const float* b0 = (const float*)d_in[2];
    const float* w1 = (const float*)d_in[3];  const float* b1 = (const float*)d_in[4];
    const float* w2 = (const float*)d_in[5];  const float* b2 = (const float*)d_in[6];
    const float* w3 = (const float*)d_in[7];  const float* b3 = (const float*)d_in[8];
    const float* w4 = (const float*)d_in[9];  const float* b4 = (const float*)d_in[10];
    const float* w5 = (const float*)d_in[11]; const float* b5 = (const float*)d_in[12];
    const float* wf = (const float*)d_in[13]; const float* bf = (const float*)d_in[14];

    int numPts = in_sizes[0] / 2;
    int numTiles = (numPts + 127) / 128;
    int grid = numTiles < MAXCTAS ? numTiles : MAXCTAS;

    siren_hmma<<<grid, BLK>>>(coords, w0, b0, w1, b1, w2, b2, w3, b3, w4, b4,
                              w5, b5, wf, bf, (float*)d_out, numPts, numTiles);
}

// round 7
// speedup vs baseline: 6.3369x; 1.3945x over previous
#include <cuda_runtime.h>
#include <cuda_fp16.h>
#include <cstdint>

#define OMEGA0 30.0f
#define BLK 128
#define MAXCTAS 888   // 148 SMs x 6 CTAs

// ---------------- helpers ----------------
__device__ __forceinline__ float fast_sigmoid(float t) {
    return __fdividef(1.0f, 1.0f + __expf(-t));
}
// pack two f32 -> f16x2 (x in low half, y in high half)
__device__ __forceinline__ uint32_t pack_f16x2(float x, float y) {
    uint32_t r;
    asm("cvt.rn.f16x2.f32 %0, %1, %2;" : "=r"(r) : "f"(y), "f"(x));
    return r;
}
// D += A * B   (m16n8k16, f16 in, f32 accum)
__device__ __forceinline__ void mma_f16(float d[4], const uint32_t a[4],
                                        uint32_t b0, uint32_t b1) {
    asm volatile(
        "mma.sync.aligned.m16n8k16.row.col.f32.f16.f16.f32 "
        "{%0,%1,%2,%3}, {%4,%5,%6,%7}, {%8,%9}, {%0,%1,%2,%3};"
        : "+f"(d[0]), "+f"(d[1]), "+f"(d[2]), "+f"(d[3])
        : "r"(a[0]), "r"(a[1]), "r"(a[2]), "r"(a[3]), "r"(b0), "r"(b1));
}

// Build A fragments (f16, no residual) for k=32 from 4 n-tiles in D layout.
#define BUILD_A(vsrc, Ah) do {                                                  \
    _Pragma("unroll")                                                           \
    for (int mt_ = 0; mt_ < 2; mt_++) {                                         \
        _Pragma("unroll")                                                       \
        for (int kt_ = 0; kt_ < 2; kt_++) {                                     \
            Ah[mt_][kt_][0] = pack_f16x2(vsrc[mt_][2*kt_][0],   vsrc[mt_][2*kt_][1]);   \
            Ah[mt_][kt_][1] = pack_f16x2(vsrc[mt_][2*kt_][2],   vsrc[mt_][2*kt_][3]);   \
            Ah[mt_][kt_][2] = pack_f16x2(vsrc[mt_][2*kt_+1][0], vsrc[mt_][2*kt_+1][1]); \
            Ah[mt_][kt_][3] = pack_f16x2(vsrc[mt_][2*kt_+1][2], vsrc[mt_][2*kt_+1][3]); \
        }                                                                       \
    }                                                                           \
} while (0)

// host-quality weight split (fill-time only): W = hi(f16) + lo(f16) to ~22 bits
__device__ __forceinline__ void split_pair_w(float x, float y, uint32_t& h, uint32_t& l) {
    __half2 hh = __floats2half2_rn(x, y);
    float hx = __low2float(hh), hy = __high2float(hh);
    __half2 ll = __floats2half2_rn(x - hx, y - hy);
    h = *(uint32_t*)&hh;
    l = *(uint32_t*)&ll;
}

__global__ void __launch_bounds__(BLK, 6)
siren_hmma(const float* __restrict__ coords,
           const float* __restrict__ w0g, const float* __restrict__ b0g,
           const float* __restrict__ w1g, const float* __restrict__ b1g,
           const float* __restrict__ w2g, const float* __restrict__ b2g,
           const float* __restrict__ w3g, const float* __restrict__ b3g,
           const float* __restrict__ w4g, const float* __restrict__ b4g,
           const float* __restrict__ w5g, const float* __restrict__ b5g,
           const float* __restrict__ wfg, const float* __restrict__ bfg,
           float* __restrict__ out, int numPts, int numTiles)
{
    // per-lane fragments, 36-word lane stride (conflict-free LDS.128)
    __shared__ __align__(16) uint32_t fragMid[4][32][36];
    __shared__ __align__(16) uint32_t frag5[32][36];
    __shared__ float2 biasM[4][16];
    __shared__ float2 bias5[8];
    __shared__ float s_w0[64], s_b0[32], s_wf[48], s_bf[3];

    const int tid = threadIdx.x;
    const int lane = tid & 31, wid = tid >> 5;
    const int t4 = lane & 3, g = lane >> 2;

    // ---- fill weight fragments (hi at [ln][q], lo at [ln][16+q]) ----
#define FILL_MID(Lc, WP)                                                       \
    for (int e = tid; e < 512; e += BLK) {                                     \
        int q = e >> 5, ln = e & 31;                                           \
        int tt = ln & 3, gg = ln >> 2;                                         \
        int kt = q >> 3, r = (q >> 2) & 1, nt = q & 3;                         \
        int k0 = kt * 16 + r * 8 + tt * 2;                                     \
        int n  = nt * 8 + gg;                                                  \
        float v0 = OMEGA0 * WP[n * 32 + k0];                                   \
        float v1 = OMEGA0 * WP[n * 32 + k0 + 1];                               \
        uint32_t h_, l_; split_pair_w(v0, v1, h_, l_);                         \
        fragMid[Lc][ln][q] = h_; fragMid[Lc][ln][16 + q] = l_;                 \
    }
    FILL_MID(0, w1g) FILL_MID(1, w2g) FILL_MID(2, w3g) FILL_MID(3, w4g)
#undef FILL_MID

    for (int e = tid; e < 256; e += BLK) {
        int q = e >> 5, ln = e & 31;
        int tt = ln & 3, gg = ln >> 2;
        int kt = q >> 2, r = (q >> 1) & 1, nt = q & 1;
        int k0 = kt * 16 + r * 8 + tt * 2;
        int n  = nt * 8 + gg;
        float v0 = OMEGA0 * w5g[n * 32 + k0];
        float v1 = OMEGA0 * w5g[n * 32 + k0 + 1];
        uint32_t h_, l_; split_pair_w(v0, v1, h_, l_);
        frag5[ln][q] = h_; frag5[ln][16 + q] = l_;
    }
#define FILL_BIAS(Lc, BP)                                                      \
    if (tid < 16) {                                                            \
        int nt = tid >> 2, tt = tid & 3;                                       \
        biasM[Lc][tid] = make_float2(OMEGA0 * BP[nt * 8 + tt * 2],             \
                                     OMEGA0 * BP[nt * 8 + tt * 2 + 1]);        \
    }
    FILL_BIAS(0, b1g) FILL_BIAS(1, b2g) FILL_BIAS(2, b3g) FILL_BIAS(3, b4g)
#undef FILL_BIAS
    if (tid < 8) {
        int nt = tid >> 2, tt = tid & 3;
        bias5[tid] = make_float2(OMEGA0 * b5g[nt * 8 + tt * 2],
                                 OMEGA0 * b5g[nt * 8 + tt * 2 + 1]);
    }
    if (tid < 64) s_w0[tid] = OMEGA0 * w0g[tid];
    if (tid < 32) s_b0[tid] = OMEGA0 * b0g[tid];
    if (tid < 48) s_wf[tid] = wfg[tid];
    if (tid < 3)  s_bf[tid] = bfg[tid];
    __syncthreads();

    // ---------------- main loop: 128 points per CTA-iter (32 per warp) ----------------
#pragma unroll 1
    for (int tile = blockIdx.x; tile < numTiles; tile += gridDim.x) {
        const int pbase = tile * 128 + wid * 32;

        float v[2][4][4];   // activation state in D-fragment layout

        // ---- layer 0: 2 -> 32, direct to fragment layout ----
#pragma unroll
        for (int mt = 0; mt < 2; mt++) {
            int p0 = pbase + mt * 16 + g;
            float2 c0 = (p0 < numPts)     ? ((const float2*)coords)[p0]     : make_float2(0.f, 0.f);
            float2 c1 = (p0 + 8 < numPts) ? ((const float2*)coords)[p0 + 8] : make_float2(0.f, 0.f);
#pragma unroll
            for (int nt = 0; nt < 4; nt++) {
                int col = nt * 8 + t4 * 2;
                float2 wa = ((const float2*)s_w0)[col];
                float2 wb = ((const float2*)s_w0)[col + 1];
                float ba = s_b0[col], bb_ = s_b0[col + 1];
                v[mt][nt][0] = __sinf(fmaf(c0.x, wa.x, fmaf(c0.y, wa.y, ba)));
                v[mt][nt][1] = __sinf(fmaf(c0.x, wb.x, fmaf(c0.y, wb.y, bb_)));
                v[mt][nt][2] = __sinf(fmaf(c1.x, wa.x, fmaf(c1.y, wa.y, ba)));
                v[mt][nt][3] = __sinf(fmaf(c1.x, wb.x, fmaf(c1.y, wb.y, bb_)));
            }
        }

        // ---- 4 middle layers 32 -> 32 on HMMA (2 passes: W_hi, W_lo) ----
#pragma unroll 1
        for (int L = 0; L < 4; L++) {
            uint32_t Ah[2][2][4];
            BUILD_A(v, Ah);

            uint32_t B[16];
            {
                const uint4* bp = (const uint4*)&fragMid[L][lane][0];
                uint4 b0_ = bp[0], b1_ = bp[1], b2_ = bp[2], b3_ = bp[3];
                B[0]=b0_.x; B[1]=b0_.y; B[2]=b0_.z; B[3]=b0_.w;
                B[4]=b1_.x; B[5]=b1_.y; B[6]=b1_.z; B[7]=b1_.w;
                B[8]=b2_.x; B[9]=b2_.y; B[10]=b2_.z; B[11]=b2_.w;
                B[12]=b3_.x; B[13]=b3_.y; B[14]=b3_.z; B[15]=b3_.w;
            }
            // init accumulators with bias
#pragma unroll
            for (int nt = 0; nt < 4; nt++) {
                float2 bb = biasM[L][nt * 4 + t4];
#pragma unroll
                for (int mt = 0; mt < 2; mt++) {
                    v[mt][nt][0] = bb.x; v[mt][nt][1] = bb.y;
                    v[mt][nt][2] = bb.x; v[mt][nt][3] = bb.y;
                }
            }
            // pass 1: x * W_hi
#pragma unroll
            for (int mt = 0; mt < 2; mt++)
#pragma unroll
                for (int nt = 0; nt < 4; nt++)
#pragma unroll
                    for (int kt = 0; kt < 2; kt++)
                        mma_f16(v[mt][nt], Ah[mt][kt], B[kt * 8 + nt], B[kt * 8 + 4 + nt]);
            // pass 2: x * W_lo
            {
                const uint4* bp = (const uint4*)&fragMid[L][lane][16];
                uint4 b0_ = bp[0], b1_ = bp[1], b2_ = bp[2], b3_ = bp[3];
                B[0]=b0_.x; B[1]=b0_.y; B[2]=b0_.z; B[3]=b0_.w;
                B[4]=b1_.x; B[5]=b1_.y; B[6]=b1_.z; B[7]=b1_.w;
                B[8]=b2_.x; B[9]=b2_.y; B[10]=b2_.z; B[11]=b2_.w;
                B[12]=b3_.x; B[13]=b3_.y; B[14]=b3_.z; B[15]=b3_.w;
            }
#pragma unroll
            for (int mt = 0; mt < 2; mt++)
#pragma unroll
                for (int nt = 0; nt < 4; nt++)
#pragma unroll
                    for (int kt = 0; kt < 2; kt++)
                        mma_f16(v[mt][nt], Ah[mt][kt], B[kt * 8 + nt], B[kt * 8 + 4 + nt]);
            // sine
#pragma unroll
            for (int mt = 0; mt < 2; mt++)
#pragma unroll
                for (int nt = 0; nt < 4; nt++)
#pragma unroll
                    for (int i = 0; i < 4; i++)
                        v[mt][nt][i] = __sinf(v[mt][nt][i]);
        }

        // ---- layer 5: 32 -> 16 on HMMA ----
        {
            uint32_t Ah[2][2][4];
            BUILD_A(v, Ah);

            uint32_t B5[8];
            {
                const uint4* bp = (const uint4*)&frag5[lane][0];
                uint4 b0_ = bp[0], b1_ = bp[1];
                B5[0]=b0_.x; B5[1]=b0_.y; B5[2]=b0_.z; B5[3]=b0_.w;
                B5[4]=b1_.x; B5[5]=b1_.y; B5[6]=b1_.z; B5[7]=b1_.w;
            }
#pragma unroll
            for (int nt = 0; nt < 2; nt++) {
                float2 bb = bias5[nt * 4 + t4];
#pragma unroll
                for (int mt = 0; mt < 2; mt++) {
                    v[mt][nt][0] = bb.x; v[mt][nt][1] = bb.y;
                    v[mt][nt][2] = bb.x; v[mt][nt][3] = bb.y;
                }
            }
#pragma unroll
            for (int mt = 0; mt < 2; mt++)
#pragma unroll
                for (int nt = 0; nt < 2; nt++)
#pragma unroll
                    for (int kt = 0; kt < 2; kt++)
                        mma_f16(v[mt][nt], Ah[mt][kt], B5[kt * 4 + nt], B5[kt * 4 + 2 + nt]);
            {
                const uint4* bp = (const uint4*)&frag5[lane][16];
                uint4 b0_ = bp[0], b1_ = bp[1];
                B5[0]=b0_.x; B5[1]=b0_.y; B5[2]=b0_.z; B5[3]=b0_.w;
                B5[4]=b1_.x; B5[5]=b1_.y; B5[6]=b1_.z; B5[7]=b1_.w;
            }
#pragma unroll
            for (int mt = 0; mt < 2; mt++)
#pragma unroll
                for (int nt = 0; nt < 2; nt++)
#pragma unroll
                    for (int kt = 0; kt < 2; kt++)
                        mma_f16(v[mt][nt], Ah[mt][kt], B5[kt * 4 + nt], B5[kt * 4 + 2 + nt]);
#pragma unroll
            for (int mt = 0; mt < 2; mt++)
#pragma unroll
                for (int nt = 0; nt < 2; nt++)
#pragma unroll
                    for (int i = 0; i < 4; i++)
                        v[mt][nt][i] = __sinf(v[mt][nt][i]);
        }

        // ---- final 16 -> 3 + sigmoid: per-lane partials + butterfly reduce ----
#pragma unroll
        for (int mt = 0; mt < 2; mt++) {
            float s[2][3];
#pragma unroll
            for (int c = 0; c < 3; c++) {
                float2 wa = ((const float2*)s_wf)[c * 8 + t4];
                float2 wb = ((const float2*)s_wf)[c * 8 + 4 + t4];
#pragma unroll
                for (int r = 0; r < 2; r++) {
                    float acc = v[mt][0][2 * r]     * wa.x
                              + v[mt][0][2 * r + 1] * wa.y
                              + v[mt][1][2 * r]     * wb.x
                              + v[mt][1][2 * r + 1] * wb.y;
                    acc += __shfl_xor_sync(0xffffffffu, acc, 1);
                    acc += __shfl_xor_sync(0xffffffffu, acc, 2);
                    s[r][c] = acc + s_bf[c];
                }
            }
            if (t4 < 3) {
#pragma unroll
                for (int r = 0; r < 2; r++) {
                    int p = pbase + mt * 16 + g + 8 * r;
                    if (p < numPts) {
                        float val = (t4 == 0) ? s[r][0] : ((t4 == 1) ? s[r][1] : s[r][2]);
                        out[(size_t)p * 3 + t4] = fast_sigmoid(val);
                    }
                }
            }
        }
    }
}

extern "C" void kernel_launch(void* const* d_in, const int* in_sizes, int n_in,
                              void* d_out, int out_size)
{
    const float* coords = (const float*)d_in[0];
    const float* w0 = (const float*)d_in[1];  const float* b0 = (const float*)d_in[2];
    const float* w1 = (const float*)d_in[3];  const float* b1 = (const float*)d_in[4];
    const float* w2 = (const float*)d_in[5];  const float* b2 = (const float*)d_in[6];
    const float* w3 = (const float*)d_in[7];  const float* b3 = (const float*)d_in[8];
    const float* w4 = (const float*)d_in[9];  const float* b4 = (const float*)d_in[10];
    const float* w5 = (const float*)d_in[11]; const float* b5 = (const float*)d_in[12];
    const float* wf = (const float*)d_in[13]; const float* bf = (const float*)d_in[14];

    int numPts = in_sizes[0] / 2;
    int numTiles = (numPts + 127) / 128;
    int grid = numTiles < MAXCTAS ? numTiles : MAXCTAS;

    siren_hmma<<<grid, BLK>>>(coords, w0, b0, w1, b1, w2, b2, w3, b3, w4, b4,
                              w5, b5, wf, bf, (float*)d_out, numPts, numTiles);
}

// round 8
// speedup vs baseline: 7.5360x; 1.1892x over previous
#include <cuda_runtime.h>
#include <cuda_fp16.h>
#include <cstdint>

#define OMEGA0 30.0f
#define BLK 128
#define MAXCTAS 888   // 148 SMs x 6 CTAs

// ---------------- helpers ----------------
__device__ __forceinline__ float fast_sigmoid(float t) {
    return __fdividef(1.0f, 1.0f + __expf(-t));
}
// pack two f32 -> f16x2 (x in low half, y in high half)
__device__ __forceinline__ uint32_t pack_f16x2(float x, float y) {
    uint32_t r;
    asm("cvt.rn.f16x2.f32 %0, %1, %2;" : "=r"(r) : "f"(y), "f"(x));
    return r;
}
// D += A * B   (m16n8k16, f16 in, f32 accum)
__device__ __forceinline__ void mma_f16(float d[4], const uint32_t a[4],
                                        uint32_t b0, uint32_t b1) {
    asm volatile(
        "mma.sync.aligned.m16n8k16.row.col.f32.f16.f16.f32 "
        "{%0,%1,%2,%3}, {%4,%5,%6,%7}, {%8,%9}, {%0,%1,%2,%3};"
        : "+f"(d[0]), "+f"(d[1]), "+f"(d[2]), "+f"(d[3])
        : "r"(a[0]), "r"(a[1]), "r"(a[2]), "r"(a[3]), "r"(b0), "r"(b1));
}

// Build A fragments (f16) for k=32 from 4 n-tiles of fp32 values in D layout.
#define BUILD_A(vsrc, Ah) do {                                                  \
    _Pragma("unroll")                                                           \
    for (int mt_ = 0; mt_ < 2; mt_++) {                                         \
        _Pragma("unroll")                                                       \
        for (int kt_ = 0; kt_ < 2; kt_++) {                                     \
            Ah[mt_][kt_][0] = pack_f16x2(vsrc[mt_][2*kt_][0],   vsrc[mt_][2*kt_][1]);   \
            Ah[mt_][kt_][1] = pack_f16x2(vsrc[mt_][2*kt_][2],   vsrc[mt_][2*kt_][3]);   \
            Ah[mt_][kt_][2] = pack_f16x2(vsrc[mt_][2*kt_+1][0], vsrc[mt_][2*kt_+1][1]); \
            Ah[mt_][kt_][3] = pack_f16x2(vsrc[mt_][2*kt_+1][2], vsrc[mt_][2*kt_+1][3]); \
        }                                                                       \
    }                                                                           \
} while (0)

// Fragment smem: per-lane contiguous.
// mid: 16 words/lane, 20-word stride -> LDS.128 bank offsets {0,20,8,28,16,4,24,12}: conflict-free.
// l5 :  8 words/lane, 12-word stride -> offsets {0,12,24,4,16,28,8,20}: conflict-free.

__global__ void __launch_bounds__(BLK, 6)
siren_hmma(const float* __restrict__ coords,
           const float* __restrict__ w0g, const float* __restrict__ b0g,
           const float* __restrict__ w1g, const float* __restrict__ b1g,
           const float* __restrict__ w2g, const float* __restrict__ b2g,
           const float* __restrict__ w3g, const float* __restrict__ b3g,
           const float* __restrict__ w4g, const float* __restrict__ b4g,
           const float* __restrict__ w5g, const float* __restrict__ b5g,
           const float* __restrict__ wfg, const float* __restrict__ bfg,
           float* __restrict__ out, int numPts, int numTiles)
{
    __shared__ __align__(16) uint32_t fragMid[4][32][20];
    __shared__ __align__(16) uint32_t frag5[32][12];
    __shared__ float2 biasM[4][16];
    __shared__ float2 bias5[8];
    __shared__ float s_w0[64], s_b0[32], s_wf[48], s_bf[3];

    const int tid = threadIdx.x;
    const int lane = tid & 31, wid = tid >> 5;
    const int t4 = lane & 3, g = lane >> 2;

    // ---- fill weight fragments (f16, single precision level) ----
#define FILL_MID(Lc, WP)                                                       \
    for (int e = tid; e < 512; e += BLK) {                                     \
        int q = e >> 5, ln = e & 31;                                           \
        int tt = ln & 3, gg = ln >> 2;                                         \
        int kt = q >> 3, r = (q >> 2) & 1, nt = q & 3;                         \
        int k0 = kt * 16 + r * 8 + tt * 2;                                     \
        int n  = nt * 8 + gg;                                                  \
        fragMid[Lc][ln][q] = pack_f16x2(OMEGA0 * WP[n * 32 + k0],              \
                                        OMEGA0 * WP[n * 32 + k0 + 1]);         \
    }
    FILL_MID(0, w1g) FILL_MID(1, w2g) FILL_MID(2, w3g) FILL_MID(3, w4g)
#undef FILL_MID

    for (int e = tid; e < 256; e += BLK) {
        int q = e >> 5, ln = e & 31;
        int tt = ln & 3, gg = ln >> 2;
        int kt = q >> 2, r = (q >> 1) & 1, nt = q & 1;
        int k0 = kt * 16 + r * 8 + tt * 2;
        int n  = nt * 8 + gg;
        frag5[ln][q] = pack_f16x2(OMEGA0 * w5g[n * 32 + k0],
                                  OMEGA0 * w5g[n * 32 + k0 + 1]);
    }
#define FILL_BIAS(Lc, BP)                                                      \
    if (tid < 16) {                                                            \
        int nt = tid >> 2, tt = tid & 3;                                       \
        biasM[Lc][tid] = make_float2(OMEGA0 * BP[nt * 8 + tt * 2],             \
                                     OMEGA0 * BP[nt * 8 + tt * 2 + 1]);        \
    }
    FILL_BIAS(0, b1g) FILL_BIAS(1, b2g) FILL_BIAS(2, b3g) FILL_BIAS(3, b4g)
#undef FILL_BIAS
    if (tid < 8) {
        int nt = tid >> 2, tt = tid & 3;
        bias5[tid] = make_float2(OMEGA0 * b5g[nt * 8 + tt * 2],
                                 OMEGA0 * b5g[nt * 8 + tt * 2 + 1]);
    }
    if (tid < 64) s_w0[tid] = OMEGA0 * w0g[tid];
    if (tid < 32) s_b0[tid] = OMEGA0 * b0g[tid];
    if (tid < 48) s_wf[tid] = wfg[tid];
    if (tid < 3)  s_bf[tid] = bfg[tid];
    __syncthreads();

    // ---------------- main loop: 128 points per CTA-iter (32 per warp) ----------------
#pragma unroll 1
    for (int tile = blockIdx.x; tile < numTiles; tile += gridDim.x) {
        const int pbase = tile * 128 + wid * 32;

        float v[2][4][4];   // activation state in D-fragment layout

        // ---- layer 0: 2 -> 32, direct to fragment layout ----
#pragma unroll
        for (int mt = 0; mt < 2; mt++) {
            int p0 = pbase + mt * 16 + g;
            float2 c0 = (p0 < numPts)     ? ((const float2*)coords)[p0]     : make_float2(0.f, 0.f);
            float2 c1 = (p0 + 8 < numPts) ? ((const float2*)coords)[p0 + 8] : make_float2(0.f, 0.f);
#pragma unroll
            for (int nt = 0; nt < 4; nt++) {
                int col = nt * 8 + t4 * 2;
                float2 wa = ((const float2*)s_w0)[col];
                float2 wb = ((const float2*)s_w0)[col + 1];
                float ba = s_b0[col], bb_ = s_b0[col + 1];
                v[mt][nt][0] = __sinf(fmaf(c0.x, wa.x, fmaf(c0.y, wa.y, ba)));
                v[mt][nt][1] = __sinf(fmaf(c0.x, wb.x, fmaf(c0.y, wb.y, bb_)));
                v[mt][nt][2] = __sinf(fmaf(c1.x, wa.x, fmaf(c1.y, wa.y, ba)));
                v[mt][nt][3] = __sinf(fmaf(c1.x, wb.x, fmaf(c1.y, wb.y, bb_)));
            }
        }

        // ---- 4 middle layers 32 -> 32 on HMMA (single f16 pass) ----
#pragma unroll 1
        for (int L = 0; L < 4; L++) {
            uint32_t Ah[2][2][4];
            BUILD_A(v, Ah);

            uint32_t B[16];
            {
                const uint4* bp = (const uint4*)&fragMid[L][lane][0];
                uint4 b0_ = bp[0], b1_ = bp[1], b2_ = bp[2], b3_ = bp[3];
                B[0]=b0_.x; B[1]=b0_.y; B[2]=b0_.z; B[3]=b0_.w;
                B[4]=b1_.x; B[5]=b1_.y; B[6]=b1_.z; B[7]=b1_.w;
                B[8]=b2_.x; B[9]=b2_.y; B[10]=b2_.z; B[11]=b2_.w;
                B[12]=b3_.x; B[13]=b3_.y; B[14]=b3_.z; B[15]=b3_.w;
            }
            // init accumulators with bias
#pragma unroll
            for (int nt = 0; nt < 4; nt++) {
                float2 bb = biasM[L][nt * 4 + t4];
#pragma unroll
                for (int mt = 0; mt < 2; mt++) {
                    v[mt][nt][0] = bb.x; v[mt][nt][1] = bb.y;
                    v[mt][nt][2] = bb.x; v[mt][nt][3] = bb.y;
                }
            }
#pragma unroll
            for (int mt = 0; mt < 2; mt++)
#pragma unroll
                for (int nt = 0; nt < 4; nt++)
#pragma unroll
                    for (int kt = 0; kt < 2; kt++)
                        mma_f16(v[mt][nt], Ah[mt][kt], B[kt * 8 + nt], B[kt * 8 + 4 + nt]);
            // sine
#pragma unroll
            for (int mt = 0; mt < 2; mt++)
#pragma unroll
                for (int nt = 0; nt < 4; nt++)
#pragma unroll
                    for (int i = 0; i < 4; i++)
                        v[mt][nt][i] = __sinf(v[mt][nt][i]);
        }

        // ---- layer 5: 32 -> 16 on HMMA ----
        {
            uint32_t Ah[2][2][4];
            BUILD_A(v, Ah);

            uint32_t B5[8];
            {
                const uint4* bp = (const uint4*)&frag5[lane][0];
                uint4 b0_ = bp[0], b1_ = bp[1];
                B5[0]=b0_.x; B5[1]=b0_.y; B5[2]=b0_.z; B5[3]=b0_.w;
                B5[4]=b1_.x; B5[5]=b1_.y; B5[6]=b1_.z; B5[7]=b1_.w;
            }
#pragma unroll
            for (int nt = 0; nt < 2; nt++) {
                float2 bb = bias5[nt * 4 + t4];
#pragma unroll
                for (int mt = 0; mt < 2; mt++) {
                    v[mt][nt][0] = bb.x; v[mt][nt][1] = bb.y;
                    v[mt][nt][2] = bb.x; v[mt][nt][3] = bb.y;
                }
            }
#pragma unroll
            for (int mt = 0; mt < 2; mt++)
#pragma unroll
                for (int nt = 0; nt < 2; nt++)
#pragma unroll
                    for (int kt = 0; kt < 2; kt++)
                        mma_f16(v[mt][nt], Ah[mt][kt], B5[kt * 4 + nt], B5[kt * 4 + 2 + nt]);
#pragma unroll
            for (int mt = 0; mt < 2; mt++)
#pragma unroll
                for (int nt = 0; nt < 2; nt++)
#pragma unroll
                    for (int i = 0; i < 4; i++)
                        v[mt][nt][i] = __sinf(v[mt][nt][i]);
        }

        // ---- final 16 -> 3 + sigmoid: per-lane partials + butterfly reduce ----
#pragma unroll
        for (int mt = 0; mt < 2; mt++) {
            float s[2][3];
#pragma unroll
            for (int c = 0; c < 3; c++) {
                float2 wa = ((const float2*)s_wf)[c * 8 + t4];
                float2 wb = ((const float2*)s_wf)[c * 8 + 4 + t4];
#pragma unroll
                for (int r = 0; r < 2; r++) {
                    float acc = v[mt][0][2 * r]     * wa.x
                              + v[mt][0][2 * r + 1] * wa.y
                              + v[mt][1][2 * r]     * wb.x
                              + v[mt][1][2 * r + 1] * wb.y;
                    acc += __shfl_xor_sync(0xffffffffu, acc, 1);
                    acc += __shfl_xor_sync(0xffffffffu, acc, 2);
                    s[r][c] = acc + s_bf[c];
                }
            }
            if (t4 < 3) {
#pragma unroll
                for (int r = 0; r < 2; r++) {
                    int p = pbase + mt * 16 + g + 8 * r;
                    if (p < numPts) {
                        float val = (t4 == 0) ? s[r][0] : ((t4 == 1) ? s[r][1] : s[r][2]);
                        out[(size_t)p * 3 + t4] = fast_sigmoid(val);
                    }
                }
            }
        }
    }
}

extern "C" void kernel_launch(void* const* d_in, const int* in_sizes, int n_in,
                              void* d_out, int out_size)
{
    const float* coords = (const float*)d_in[0];
    const float* w0 = (const float*)d_in[1];  const float* b0 = (const float*)d_in[2];
    const float* w1 = (const float*)d_in[3];  const float* b1 = (const float*)d_in[4];
    const float* w2 = (const float*)d_in[5];  const float* b2 = (const float*)d_in[6];
    const float* w3 = (const float*)d_in[7];  const float* b3 = (const float*)d_in[8];
    const float* w4 = (const float*)d_in[9];  const float* b4 = (const float*)d_in[10];
    const float* w5 = (const float*)d_in[11]; const float* b5 = (const float*)d_in[12];
    const float* wf = (const float*)d_in[13]; const float* bf = (const float*)d_in[14];

    int numPts = in_sizes[0] / 2;
    int numTiles = (numPts + 127) / 128;
    int grid = numTiles < MAXCTAS ? numTiles : MAXCTAS;

    siren_hmma<<<grid, BLK>>>(coords, w0, b0, w1, b1, w2, b2, w3, b3, w4, b4,
                              w5, b5, wf, bf, (float*)d_out, numPts, numTiles);
}

// round 9
// speedup vs baseline: 7.6304x; 1.0125x over previous
#include <cuda_runtime.h>
#include <cuda_fp16.h>
#include <cstdint>

#define OMEGA0 30.0f
#define BLK 128
#define MAXCTAS 888   // 148 SMs x 6 CTAs

// ---------------- helpers ----------------
__device__ __forceinline__ float fast_sigmoid(float t) {
    return __fdividef(1.0f, 1.0f + __expf(-t));
}
// pack two f32 -> f16x2 (x in low half, y in high half)
__device__ __forceinline__ uint32_t pack_f16x2(float x, float y) {
    uint32_t r;
    asm("cvt.rn.f16x2.f32 %0, %1, %2;" : "=r"(r) : "f"(y), "f"(x));
    return r;
}
// D += A * B   (accumulate in place)
__device__ __forceinline__ void mma_f16(float d[4], const uint32_t a[4],
                                        uint32_t b0, uint32_t b1) {
    asm volatile(
        "mma.sync.aligned.m16n8k16.row.col.f32.f16.f16.f32 "
        "{%0,%1,%2,%3}, {%4,%5,%6,%7}, {%8,%9}, {%0,%1,%2,%3};"
        : "+f"(d[0]), "+f"(d[1]), "+f"(d[2]), "+f"(d[3])
        : "r"(a[0]), "r"(a[1]), "r"(a[2]), "r"(a[3]), "r"(b0), "r"(b1));
}
// D = A * B + {c0,c1,c0,c1}   (bias injected via C operand, no MOVs)
__device__ __forceinline__ void mma_f16_bias(float d[4], const uint32_t a[4],
                                             uint32_t b0, uint32_t b1,
                                             float c0, float c1) {
    asm volatile(
        "mma.sync.aligned.m16n8k16.row.col.f32.f16.f16.f32 "
        "{%0,%1,%2,%3}, {%4,%5,%6,%7}, {%8,%9}, {%10,%11,%10,%11};"
        : "=f"(d[0]), "=f"(d[1]), "=f"(d[2]), "=f"(d[3])
        : "r"(a[0]), "r"(a[1]), "r"(a[2]), "r"(a[3]), "r"(b0), "r"(b1),
          "f"(c0), "f"(c1));
}

// Build A fragments (f16) for k=32 from 4 n-tiles of fp32 values in D layout.
#define BUILD_A(vsrc, Ah) do {                                                  \
    _Pragma("unroll")                                                           \
    for (int mt_ = 0; mt_ < 2; mt_++) {                                         \
        _Pragma("unroll")                                                       \
        for (int kt_ = 0; kt_ < 2; kt_++) {                                     \
            Ah[mt_][kt_][0] = pack_f16x2(vsrc[mt_][2*kt_][0],   vsrc[mt_][2*kt_][1]);   \
            Ah[mt_][kt_][1] = pack_f16x2(vsrc[mt_][2*kt_][2],   vsrc[mt_][2*kt_][3]);   \
            Ah[mt_][kt_][2] = pack_f16x2(vsrc[mt_][2*kt_+1][0], vsrc[mt_][2*kt_+1][1]); \
            Ah[mt_][kt_][3] = pack_f16x2(vsrc[mt_][2*kt_+1][2], vsrc[mt_][2*kt_+1][3]); \
        }                                                                       \
    }                                                                           \
} while (0)

__global__ void __launch_bounds__(BLK, 6)
siren_hmma(const float* __restrict__ coords,
           const float* __restrict__ w0g, const float* __restrict__ b0g,
           const float* __restrict__ w1g, const float* __restrict__ b1g,
           const float* __restrict__ w2g, const float* __restrict__ b2g,
           const float* __restrict__ w3g, const float* __restrict__ b3g,
           const float* __restrict__ w4g, const float* __restrict__ b4g,
           const float* __restrict__ w5g, const float* __restrict__ b5g,
           const float* __restrict__ wfg, const float* __restrict__ bfg,
           float* __restrict__ out, int numPts, int numTiles)
{
    __shared__ __align__(16) uint32_t fragMid[4][32][20];
    __shared__ __align__(16) uint32_t frag5[32][12];
    __shared__ float2 biasM[4][16];
    __shared__ float2 bias5[8];
    __shared__ float s_w0[64], s_b0[32], s_wf[48], s_bf[3];

    const int tid = threadIdx.x;
    const int lane = tid & 31, wid = tid >> 5;
    const int t4 = lane & 3, g = lane >> 2;

    // ---- fill weight fragments ----
#define FILL_MID(Lc, WP)                                                       \
    for (int e = tid; e < 512; e += BLK) {                                     \
        int q = e >> 5, ln = e & 31;                                           \
        int tt = ln & 3, gg = ln >> 2;                                         \
        int kt = q >> 3, r = (q >> 2) & 1, nt = q & 3;                         \
        int k0 = kt * 16 + r * 8 + tt * 2;                                     \
        int n  = nt * 8 + gg;                                                  \
        fragMid[Lc][ln][q] = pack_f16x2(OMEGA0 * WP[n * 32 + k0],              \
                                        OMEGA0 * WP[n * 32 + k0 + 1]);         \
    }
    FILL_MID(0, w1g) FILL_MID(1, w2g) FILL_MID(2, w3g) FILL_MID(3, w4g)
#undef FILL_MID

    for (int e = tid; e < 256; e += BLK) {
        int q = e >> 5, ln = e & 31;
        int tt = ln & 3, gg = ln >> 2;
        int kt = q >> 2, r = (q >> 1) & 1, nt = q & 1;
        int k0 = kt * 16 + r * 8 + tt * 2;
        int n  = nt * 8 + gg;
        frag5[ln][q] = pack_f16x2(OMEGA0 * w5g[n * 32 + k0],
                                  OMEGA0 * w5g[n * 32 + k0 + 1]);
    }
#define FILL_BIAS(Lc, BP)                                                      \
    if (tid < 16) {                                                            \
        int nt = tid >> 2, tt = tid & 3;                                       \
        biasM[Lc][tid] = make_float2(OMEGA0 * BP[nt * 8 + tt * 2],             \
                                     OMEGA0 * BP[nt * 8 + tt * 2 + 1]);        \
    }
    FILL_BIAS(0, b1g) FILL_BIAS(1, b2g) FILL_BIAS(2, b3g) FILL_BIAS(3, b4g)
#undef FILL_BIAS
    if (tid < 8) {
        int nt = tid >> 2, tt = tid & 3;
        bias5[tid] = make_float2(OMEGA0 * b5g[nt * 8 + tt * 2],
                                 OMEGA0 * b5g[nt * 8 + tt * 2 + 1]);
    }
    if (tid < 64) s_w0[tid] = OMEGA0 * w0g[tid];
    if (tid < 32) s_b0[tid] = OMEGA0 * b0g[tid];
    if (tid < 48) s_wf[tid] = wfg[tid];
    if (tid < 3)  s_bf[tid] = bfg[tid];
    __syncthreads();

    // ---------------- main loop: 128 points per CTA-iter (32 per warp) ----------------
#pragma unroll 1
    for (int tile = blockIdx.x; tile < numTiles; tile += gridDim.x) {
        const int pbase = tile * 128 + wid * 32;

        float v[2][4][4];   // activation state in D-fragment layout

        // ---- layer 0: 2 -> 32, direct to fragment layout ----
#pragma unroll
        for (int mt = 0; mt < 2; mt++) {
            int p0 = pbase + mt * 16 + g;
            float2 c0 = (p0 < numPts)     ? ((const float2*)coords)[p0]     : make_float2(0.f, 0.f);
            float2 c1 = (p0 + 8 < numPts) ? ((const float2*)coords)[p0 + 8] : make_float2(0.f, 0.f);
#pragma unroll
            for (int nt = 0; nt < 4; nt++) {
                int col = nt * 8 + t4 * 2;
                float2 wa = ((const float2*)s_w0)[col];
                float2 wb = ((const float2*)s_w0)[col + 1];
                float ba = s_b0[col], bb_ = s_b0[col + 1];
                v[mt][nt][0] = __sinf(fmaf(c0.x, wa.x, fmaf(c0.y, wa.y, ba)));
                v[mt][nt][1] = __sinf(fmaf(c0.x, wb.x, fmaf(c0.y, wb.y, bb_)));
                v[mt][nt][2] = __sinf(fmaf(c1.x, wa.x, fmaf(c1.y, wa.y, ba)));
                v[mt][nt][3] = __sinf(fmaf(c1.x, wb.x, fmaf(c1.y, wb.y, bb_)));
            }
        }

        // ---- 4 middle layers 32 -> 32 on HMMA ----
#pragma unroll 1
        for (int L = 0; L < 4; L++) {
            uint32_t Ah[2][2][4];
            BUILD_A(v, Ah);

            uint32_t B[16];
            {
                const uint4* bp = (const uint4*)&fragMid[L][lane][0];
                uint4 b0_ = bp[0], b1_ = bp[1], b2_ = bp[2], b3_ = bp[3];
                B[0]=b0_.x; B[1]=b0_.y; B[2]=b0_.z; B[3]=b0_.w;
                B[4]=b1_.x; B[5]=b1_.y; B[6]=b1_.z; B[7]=b1_.w;
                B[8]=b2_.x; B[9]=b2_.y; B[10]=b2_.z; B[11]=b2_.w;
                B[12]=b3_.x; B[13]=b3_.y; B[14]=b3_.z; B[15]=b3_.w;
            }
            // kt=0 with bias injected via C operand; kt=1 accumulates
#pragma unroll
            for (int nt = 0; nt < 4; nt++) {
                float2 bb = biasM[L][nt * 4 + t4];
#pragma unroll
                for (int mt = 0; mt < 2; mt++) {
                    mma_f16_bias(v[mt][nt], Ah[mt][0], B[nt], B[4 + nt], bb.x, bb.y);
                    mma_f16     (v[mt][nt], Ah[mt][1], B[8 + nt], B[12 + nt]);
                }
            }
            // sine
#pragma unroll
            for (int mt = 0; mt < 2; mt++)
#pragma unroll
                for (int nt = 0; nt < 4; nt++)
#pragma unroll
                    for (int i = 0; i < 4; i++)
                        v[mt][nt][i] = __sinf(v[mt][nt][i]);
        }

        // ---- layer 5: 32 -> 16 on HMMA ----
        {
            uint32_t Ah[2][2][4];
            BUILD_A(v, Ah);

            uint32_t B5[8];
            {
                const uint4* bp = (const uint4*)&frag5[lane][0];
                uint4 b0_ = bp[0], b1_ = bp[1];
                B5[0]=b0_.x; B5[1]=b0_.y; B5[2]=b0_.z; B5[3]=b0_.w;
                B5[4]=b1_.x; B5[5]=b1_.y; B5[6]=b1_.z; B5[7]=b1_.w;
            }
#pragma unroll
            for (int nt = 0; nt < 2; nt++) {
                float2 bb = bias5[nt * 4 + t4];
#pragma unroll
                for (int mt = 0; mt < 2; mt++) {
                    mma_f16_bias(v[mt][nt], Ah[mt][0], B5[nt], B5[2 + nt], bb.x, bb.y);
                    mma_f16     (v[mt][nt], Ah[mt][1], B5[4 + nt], B5[6 + nt]);
                }
            }
#pragma unroll
            for (int mt = 0; mt < 2; mt++)
#pragma unroll
                for (int nt = 0; nt < 2; nt++)
#pragma unroll
                    for (int i = 0; i < 4; i++)
                        v[mt][nt][i] = __sinf(v[mt][nt][i]);
        }

        // ---- final 16 -> 3 + sigmoid: per-lane partials + butterfly reduce ----
#pragma unroll
        for (int mt = 0; mt < 2; mt++) {
            float s[2][3];
#pragma unroll
            for (int c = 0; c < 3; c++) {
                float2 wa = ((const float2*)s_wf)[c * 8 + t4];
                float2 wb = ((const float2*)s_wf)[c * 8 + 4 + t4];
#pragma unroll
                for (int r = 0; r < 2; r++) {
                    float acc = v[mt][0][2 * r]     * wa.x
                              + v[mt][0][2 * r + 1] * wa.y
                              + v[mt][1][2 * r]     * wb.x
                              + v[mt][1][2 * r + 1] * wb.y;
                    acc += __shfl_xor_sync(0xffffffffu, acc, 1);
                    acc += __shfl_xor_sync(0xffffffffu, acc, 2);
                    s[r][c] = acc + s_bf[c];
                }
            }
            if (t4 < 3) {
#pragma unroll
                for (int r = 0; r < 2; r++) {
                    int p = pbase + mt * 16 + g + 8 * r;
                    if (p < numPts) {
                        float val = (t4 == 0) ? s[r][0] : ((t4 == 1) ? s[r][1] : s[r][2]);
                        out[(size_t)p * 3 + t4] = fast_sigmoid(val);
                    }
                }
            }
        }
    }
}

extern "C" void kernel_launch(void* const* d_in, const int* in_sizes, int n_in,
                              void* d_out, int out_size)
{
    const float* coords = (const float*)d_in[0];
    const float* w0 = (const float*)d_in[1];  const float* b0 = (const float*)d_in[2];
    const float* w1 = (const float*)d_in[3];  const float* b1 = (const float*)d_in[4];
    const float* w2 = (const float*)d_in[5];  const float* b2 = (const float*)d_in[6];
    const float* w3 = (const float*)d_in[7];  const float* b3 = (const float*)d_in[8];
    const float* w4 = (const float*)d_in[9];  const float* b4 = (const float*)d_in[10];
    const float* w5 = (const float*)d_in[11]; const float* b5 = (const float*)d_in[12];
    const float* wf = (const float*)d_in[13]; const float* bf = (const float*)d_in[14];

    int numPts = in_sizes[0] / 2;
    int numTiles = (numPts + 127) / 128;
    int grid = numTiles < MAXCTAS ? numTiles : MAXCTAS;

    siren_hmma<<<grid, BLK>>>(coords, w0, b0, w1, b1, w2, b2, w3, b3, w4, b4,
                              w5, b5, wf, bf, (float*)d_out, numPts, numTiles);
}